// round 8
// baseline (speedup 1.0000x reference)
#include <cuda_runtime.h>
#include <cstdint>

// CAN co-action unit: per-sample 2-layer MLP, D=16, N=50, B=16384.
// Persistent double-buffered TMA pipeline:
//   - 304 persistent CTAs (2/SM), each loops over ~7 tiles of 8 samples
//   - cp.async.bulk loads (x tile + 8 padded param blocks) into stage k&1,
//     prefetch for tile k+2 issued as soon as stage reads complete
//   - R3/R7 compute core: 2 same-sample rows/thread in registers, weights via
//     broadcast LDS.128 from 552-word-padded smem, rotated-chunk LDS/STS at
//     the 4-wavefront floor
//   - output: rotated STS into obuf -> dense cp.async.bulk store, drained
//     (wait_group 0) overlapped with next tile's compute
// No per-lane LDG/STG anywhere -> the 16x l1tex wavefront amplification that
// bounded R3 is gone, and unlike R7 the TMA latency is hidden by the pipeline.

#define D 16
#define N 50
#define PARAMS 544
#define PSTRIDE 552                 // padded param stride, words
#define SPC 8                       // samples per tile
#define TPS 25
#define THREADS 224
#define ACTIVE (SPC * TPS)          // 200
#define CTA_ROWS (SPC * N)          // 400
#define XW (CTA_ROWS * D)           // 6400 words per x tile
#define PW (SPC * PSTRIDE)          // 4416 words per param stage
#define X_BYTES (XW * 4)            // 25600
#define P_BYTES (PARAMS * 4)        // 2176
#define TX_TOTAL (X_BYTES + SPC * P_BYTES)   // 43008
#define GRID_MAX 304
// dyn smem: sx[2] | sp[2] | obuf | mbar[2]
#define SM_FLOATS (2 * XW + 2 * PW + XW)      // 28032
#define SMEM_BYTES (SM_FLOATS * 4 + 16)       // 112144

__device__ __forceinline__ uint32_t s2u(const void* p) {
    uint32_t a;
    asm("{ .reg .u64 t; cvta.to.shared.u64 t, %1; cvt.u32.u64 %0, t; }"
        : "=r"(a) : "l"(p));
    return a;
}

__device__ __forceinline__ void mbar_wait(uint32_t mb, int parity) {
    uint32_t done;
    asm volatile(
        "{\n\t.reg .pred p;\n\t"
        "mbarrier.try_wait.parity.acquire.cta.shared::cta.b64 p, [%1], %2;\n\t"
        "selp.b32 %0, 1, 0, p;\n\t}"
        : "=r"(done) : "r"(mb), "r"((uint32_t)parity) : "memory");
    while (!done) {
        asm volatile(
            "{\n\t.reg .pred p;\n\t"
            "mbarrier.try_wait.parity.acquire.cta.shared::cta.b64 p, [%1], %2, 0x989680;\n\t"
            "selp.b32 %0, 1, 0, p;\n\t}"
            : "=r"(done) : "r"(mb), "r"((uint32_t)parity) : "memory");
    }
}

__device__ __forceinline__ void issue_tile(
    uint32_t mb, float* sx, float* sp, int tile,
    const float* __restrict__ user_emb, const float* __restrict__ item_emb)
{
    asm volatile("mbarrier.arrive.expect_tx.shared.b64 _, [%0], %1;"
                 :: "r"(mb), "r"((uint32_t)TX_TOTAL) : "memory");
    asm volatile("cp.async.bulk.shared::cta.global.mbarrier::complete_tx::bytes"
                 " [%0], [%1], %2, [%3];"
                 :: "r"(s2u(sx)), "l"(user_emb + (size_t)tile * XW),
                    "r"((uint32_t)X_BYTES), "r"(mb) : "memory");
    #pragma unroll
    for (int q = 0; q < SPC; q++) {
        asm volatile("cp.async.bulk.shared::cta.global.mbarrier::complete_tx::bytes"
                     " [%0], [%1], %2, [%3];"
                     :: "r"(s2u(sp + q * PSTRIDE)),
                        "l"(item_emb + ((size_t)tile * SPC + q) * PARAMS),
                        "r"((uint32_t)P_BYTES), "r"(mb) : "memory");
    }
}

__global__ __launch_bounds__(THREADS, 2) void can_kernel(
    const float* __restrict__ user_emb,
    const float* __restrict__ item_emb,
    float* __restrict__ out,
    int NT)
{
    extern __shared__ float sm[];
    float* sxS[2] = { sm, sm + XW };
    float* spS[2] = { sm + 2 * XW, sm + 2 * XW + PW };
    float* obuf   = sm + 2 * XW + 2 * PW;
    uint64_t* mbar = (uint64_t*)(sm + SM_FLOATS);

    const int t = threadIdx.x;
    const int G = gridDim.x;
    const uint32_t mb0 = s2u(&mbar[0]);
    const uint32_t mb1 = s2u(&mbar[1]);

    if (t == 0) {
        asm volatile("mbarrier.init.shared.b64 [%0], 1;" :: "r"(mb0) : "memory");
        asm volatile("mbarrier.init.shared.b64 [%0], 1;" :: "r"(mb1) : "memory");
        asm volatile("fence.proxy.async.shared::cta;" ::: "memory");
    }
    __syncthreads();

    // Prologue: load tiles k=0,1 into stages 0,1.
    if (t == 0) {
        if (blockIdx.x < NT)
            issue_tile(mb0, sxS[0], spS[0], blockIdx.x, user_emb, item_emb);
        if (blockIdx.x + G < NT)
            issue_tile(mb1, sxS[1], spS[1], blockIdx.x + G, user_emb, item_emb);
    }

    const bool act = (t < ACTIVE);
    const int smp = t / TPS;            // sample in tile (0..7)
    const int j   = t - smp * TPS;      // 0..24
    const int r0  = smp * N + j;        // local rows r0, r0+25 (same sample)
    const int r1  = r0 + TPS;

    int ph[2] = {0, 0};

    for (int k = 0, tile = blockIdx.x; tile < NT; k++, tile += G) {
        const int st = k & 1;
        const uint32_t mb = st ? mb1 : mb0;
        mbar_wait(mb, ph[st]);
        ph[st] ^= 1;

        float a0[D], a1[D];
        if (act) {
            const float* xt = sxS[st];
            const float* p  = spS[st] + smp * PSTRIDE;

            // x rows -> regs, chunk-rotated LDS.128 (4-wf floor).
            float x0[D], x1[D];
            #pragma unroll
            for (int q = 0; q < 4; q++) {
                const int c0 = (q + (r0 >> 1)) & 3;
                const int c1 = (q + (r1 >> 1)) & 3;
                float4 a = *(const float4*)(xt + r0 * D + c0 * 4);
                float4 b = *(const float4*)(xt + r1 * D + c1 * 4);
                x0[4*c0+0]=a.x; x0[4*c0+1]=a.y; x0[4*c0+2]=a.z; x0[4*c0+3]=a.w;
                x1[4*c1+0]=b.x; x1[4*c1+1]=b.y; x1[4*c1+2]=b.z; x1[4*c1+3]=b.w;
            }

            // Layer 1: relu(x W0 + b0).
            {
                const float4* bias = (const float4*)(p + 256);
                #pragma unroll
                for (int q = 0; q < 4; q++) {
                    float4 v = bias[q];
                    a0[4*q+0]=v.x; a0[4*q+1]=v.y; a0[4*q+2]=v.z; a0[4*q+3]=v.w;
                    a1[4*q+0]=v.x; a1[4*q+1]=v.y; a1[4*q+2]=v.z; a1[4*q+3]=v.w;
                }
                #pragma unroll
                for (int d = 0; d < D; d++) {
                    const float4* wr = (const float4*)(p + d * D);
                    const float u0 = x0[d], u1 = x1[d];
                    #pragma unroll
                    for (int q = 0; q < 4; q++) {
                        float4 w = wr[q];
                        a0[4*q+0]=fmaf(u0,w.x,a0[4*q+0]); a1[4*q+0]=fmaf(u1,w.x,a1[4*q+0]);
                        a0[4*q+1]=fmaf(u0,w.y,a0[4*q+1]); a1[4*q+1]=fmaf(u1,w.y,a1[4*q+1]);
                        a0[4*q+2]=fmaf(u0,w.z,a0[4*q+2]); a1[4*q+2]=fmaf(u1,w.z,a1[4*q+2]);
                        a0[4*q+3]=fmaf(u0,w.w,a0[4*q+3]); a1[4*q+3]=fmaf(u1,w.w,a1[4*q+3]);
                    }
                }
                #pragma unroll
                for (int e = 0; e < D; e++) {
                    x0[e] = fmaxf(a0[e], 0.0f);
                    x1[e] = fmaxf(a1[e], 0.0f);
                }
            }

            // Layer 2: x W1 + b1.
            {
                const float4* bias = (const float4*)(p + 528);
                #pragma unroll
                for (int q = 0; q < 4; q++) {
                    float4 v = bias[q];
                    a0[4*q+0]=v.x; a0[4*q+1]=v.y; a0[4*q+2]=v.z; a0[4*q+3]=v.w;
                    a1[4*q+0]=v.x; a1[4*q+1]=v.y; a1[4*q+2]=v.z; a1[4*q+3]=v.w;
                }
                #pragma unroll
                for (int d = 0; d < D; d++) {
                    const float4* wr = (const float4*)(p + 272 + d * D);
                    const float u0 = x0[d], u1 = x1[d];
                    #pragma unroll
                    for (int q = 0; q < 4; q++) {
                        float4 w = wr[q];
                        a0[4*q+0]=fmaf(u0,w.x,a0[4*q+0]); a1[4*q+0]=fmaf(u1,w.x,a1[4*q+0]);
                        a0[4*q+1]=fmaf(u0,w.y,a0[4*q+1]); a1[4*q+1]=fmaf(u1,w.y,a1[4*q+1]);
                        a0[4*q+2]=fmaf(u0,w.z,a0[4*q+2]); a1[4*q+2]=fmaf(u1,w.z,a1[4*q+2]);
                        a0[4*q+3]=fmaf(u0,w.w,a0[4*q+3]); a1[4*q+3]=fmaf(u1,w.w,a1[4*q+3]);
                    }
                }
            }
        }

        // Drain previous obuf store (overlaps with other warps' compute).
        if (t == 0)
            asm volatile("cp.async.bulk.wait_group 0;" ::: "memory");
        __syncthreads();   // B1: stage-st reads done by all + obuf drained

        // Prefetch tile k+2 into this stage (now free).
        if (t == 0) {
            int nx = tile + 2 * G;
            if (nx < NT) issue_tile(mb, sxS[st], spS[st], nx, user_emb, item_emb);
        }

        // Results -> obuf, chunk-rotated STS.128 (dense layout preserved).
        if (act) {
            #pragma unroll
            for (int q = 0; q < 4; q++) {
                const int c0 = (q + (r0 >> 1)) & 3;
                const int c1 = (q + (r1 >> 1)) & 3;
                float4 v0 = { fmaxf(a0[4*c0+0],0.f), fmaxf(a0[4*c0+1],0.f),
                              fmaxf(a0[4*c0+2],0.f), fmaxf(a0[4*c0+3],0.f) };
                float4 v1 = { fmaxf(a1[4*c1+0],0.f), fmaxf(a1[4*c1+1],0.f),
                              fmaxf(a1[4*c1+2],0.f), fmaxf(a1[4*c1+3],0.f) };
                *(float4*)(obuf + r0 * D + c0 * 4) = v0;
                *(float4*)(obuf + r1 * D + c1 * 4) = v1;
            }
        }
        __syncthreads();   // B2: obuf complete

        if (t == 0) {
            asm volatile("fence.proxy.async.shared::cta;" ::: "memory");
            asm volatile("cp.async.bulk.global.shared::cta.bulk_group [%0], [%1], %2;"
                         :: "l"(out + (size_t)tile * XW),
                            "r"(s2u(obuf)), "r"((uint32_t)X_BYTES) : "memory");
            asm volatile("cp.async.bulk.commit_group;" ::: "memory");
        }
    }

    // Final drain before smem is released.
    if (t == 0)
        asm volatile("cp.async.bulk.wait_group 0;" ::: "memory");
}

extern "C" void kernel_launch(void* const* d_in, const int* in_sizes, int n_in,
                              void* d_out, int out_size) {
    const float* user_emb = (const float*)d_in[0];
    const float* item_emb = (const float*)d_in[1];
    float* out = (float*)d_out;
    const int B  = in_sizes[1] / PARAMS;   // 16384
    const int NT = B / SPC;                // 2048 tiles
    const int G  = NT < GRID_MAX ? NT : GRID_MAX;
    cudaFuncSetAttribute(can_kernel, cudaFuncAttributeMaxDynamicSharedMemorySize,
                         SMEM_BYTES);
    can_kernel<<<G, THREADS, SMEM_BYTES>>>(user_emb, item_emb, out, NT);
}

// round 9
// speedup vs baseline: 1.6054x; 1.6054x over previous
#include <cuda_runtime.h>
#include <cstdint>

// CAN co-action unit: per-sample 2-layer MLP, D=16, N=50, B=16384.
// R3 champion structure, single isolated change: the 16x-amplified per-thread
// STG.128 output path is replaced by rotated STS.128 into a dense smem tile
// (4-wavefront floor) + one cp.async.bulk store per CTA. Everything else
// (direct strided x LDG, broadcast weight LDS from 552-padded smem, scalar
// fmaf, 2 same-sample rows/thread, 224 thr / 8 samples / 3 CTAs/SM) is R3.

#define D 16
#define N 50
#define PARAMS 544            // 2*(256+16)
#define PSTRIDE 552           // padded param stride (words); %32==8 bank shift
#define SPC 8                 // samples per CTA
#define TPS 25                // threads per sample (2 rows each)
#define THREADS 224
#define ACTIVE (SPC * TPS)    // 200
#define CTA_ROWS (SPC * N)    // 400
#define PWORDS (SPC * PSTRIDE)   // 4416
#define XWORDS (CTA_ROWS * D)    // 6400
#define X_BYTES (XWORDS * 4)     // 25600

__device__ __forceinline__ uint32_t s2u(const void* p) {
    uint32_t a;
    asm("{ .reg .u64 t; cvta.to.shared.u64 t, %1; cvt.u32.u64 %0, t; }"
        : "=r"(a) : "l"(p));
    return a;
}

__global__ __launch_bounds__(THREADS, 3) void can_kernel(
    const float* __restrict__ user_emb,
    const float* __restrict__ item_emb,
    float* __restrict__ out)
{
    __shared__ float sp[PWORDS];                 // params, padded
    __shared__ alignas(128) float so[XWORDS];    // dense output tile

    const int t = threadIdx.x;

    // ---- Stage params for 8 samples (136 float4 each), coalesced (as R3).
    {
        const float4* src = (const float4*)(item_emb + (size_t)blockIdx.x * SPC * PARAMS);
        #pragma unroll
        for (int k = 0; k < 5; k++) {
            int i = t + k * THREADS;
            if (i < SPC * (PARAMS / 4)) {
                int si = i / (PARAMS / 4);
                int wi = i - si * (PARAMS / 4);
                *(float4*)(sp + si * PSTRIDE + wi * 4) = src[i];
            }
        }
    }

    // ---- This thread's two rows (same sample): rows j and j+25 of sample s.
    const int s = t / TPS;
    const int j = t - s * TPS;
    const bool active = (t < ACTIVE);

    const int    lrow = s * N + j;                             // local row
    const size_t grow = (size_t)blockIdx.x * CTA_ROWS + lrow;  // global row
    float x0[D], x1[D];
    if (active) {
        const float4* r0 = (const float4*)(user_emb + grow * D);
        const float4* r1 = (const float4*)(user_emb + (grow + TPS) * D);
        #pragma unroll
        for (int q = 0; q < 4; q++) {
            float4 a = r0[q], b = r1[q];
            x0[q*4+0]=a.x; x0[q*4+1]=a.y; x0[q*4+2]=a.z; x0[q*4+3]=a.w;
            x1[q*4+0]=b.x; x1[q*4+1]=b.y; x1[q*4+2]=b.z; x1[q*4+3]=b.w;
        }
    }
    __syncthreads();

    float a0[D], a1[D];

    if (active) {
        const float* p = sp + s * PSTRIDE;

        // ---- Layer 1: relu(x W0 + b0). W0 = p[0..255], b0 = p[256..271].
        {
            const float4* bias = (const float4*)(p + 256);
            #pragma unroll
            for (int q = 0; q < 4; q++) {
                float4 v = bias[q];
                a0[q*4+0]=v.x; a0[q*4+1]=v.y; a0[q*4+2]=v.z; a0[q*4+3]=v.w;
                a1[q*4+0]=v.x; a1[q*4+1]=v.y; a1[q*4+2]=v.z; a1[q*4+3]=v.w;
            }
            #pragma unroll
            for (int d = 0; d < D; d++) {
                const float4* wr = (const float4*)(p + d * D);
                const float u0 = x0[d], u1 = x1[d];
                #pragma unroll
                for (int q = 0; q < 4; q++) {
                    float4 w = wr[q];
                    a0[q*4+0]=fmaf(u0,w.x,a0[q*4+0]); a1[q*4+0]=fmaf(u1,w.x,a1[q*4+0]);
                    a0[q*4+1]=fmaf(u0,w.y,a0[q*4+1]); a1[q*4+1]=fmaf(u1,w.y,a1[q*4+1]);
                    a0[q*4+2]=fmaf(u0,w.z,a0[q*4+2]); a1[q*4+2]=fmaf(u1,w.z,a1[q*4+2]);
                    a0[q*4+3]=fmaf(u0,w.w,a0[q*4+3]); a1[q*4+3]=fmaf(u1,w.w,a1[q*4+3]);
                }
            }
            #pragma unroll
            for (int e = 0; e < D; e++) {
                x0[e] = fmaxf(a0[e], 0.0f);
                x1[e] = fmaxf(a1[e], 0.0f);
            }
        }

        // ---- Layer 2: x W1 + b1. W1 = p[272..527], b1 = p[528..543].
        {
            const float4* bias = (const float4*)(p + 528);
            #pragma unroll
            for (int q = 0; q < 4; q++) {
                float4 v = bias[q];
                a0[q*4+0]=v.x; a0[q*4+1]=v.y; a0[q*4+2]=v.z; a0[q*4+3]=v.w;
                a1[q*4+0]=v.x; a1[q*4+1]=v.y; a1[q*4+2]=v.z; a1[q*4+3]=v.w;
            }
            #pragma unroll
            for (int d = 0; d < D; d++) {
                const float4* wr = (const float4*)(p + 272 + d * D);
                const float u0 = x0[d], u1 = x1[d];
                #pragma unroll
                for (int q = 0; q < 4; q++) {
                    float4 w = wr[q];
                    a0[q*4+0]=fmaf(u0,w.x,a0[q*4+0]); a1[q*4+0]=fmaf(u1,w.x,a1[q*4+0]);
                    a0[q*4+1]=fmaf(u0,w.y,a0[q*4+1]); a1[q*4+1]=fmaf(u1,w.y,a1[q*4+1]);
                    a0[q*4+2]=fmaf(u0,w.z,a0[q*4+2]); a1[q*4+2]=fmaf(u1,w.z,a1[q*4+2]);
                    a0[q*4+3]=fmaf(u0,w.w,a0[q*4+3]); a1[q*4+3]=fmaf(u1,w.w,a1[q*4+3]);
                }
            }
        }

        // ---- Relu + rotated STS.128 into dense smem tile (4-wf floor).
        // Address = row*16 + chunk*4 words: layout is plain row-major; the
        // rotation only permutes issue order so each instruction's 32 lanes
        // cover all 32 banks exactly once per 8-lane group.
        const int r0i = lrow, r1i = lrow + TPS;
        #pragma unroll
        for (int q = 0; q < 4; q++) {
            const int c0 = (q + (r0i >> 1)) & 3;
            const int c1 = (q + (r1i >> 1)) & 3;
            float4 v0 = { fmaxf(a0[4*c0+0],0.f), fmaxf(a0[4*c0+1],0.f),
                          fmaxf(a0[4*c0+2],0.f), fmaxf(a0[4*c0+3],0.f) };
            float4 v1 = { fmaxf(a1[4*c1+0],0.f), fmaxf(a1[4*c1+1],0.f),
                          fmaxf(a1[4*c1+2],0.f), fmaxf(a1[4*c1+3],0.f) };
            *(float4*)(so + r0i * D + c0 * 4) = v0;
            *(float4*)(so + r1i * D + c1 * 4) = v1;
        }
    }
    __syncthreads();

    // ---- One dense bulk store for the whole CTA tile.
    if (t == 0) {
        asm volatile("fence.proxy.async.shared::cta;" ::: "memory");
        asm volatile("cp.async.bulk.global.shared::cta.bulk_group [%0], [%1], %2;"
                     :: "l"(out + (size_t)blockIdx.x * CTA_ROWS * D),
                        "r"(s2u(so)), "r"((uint32_t)X_BYTES) : "memory");
        asm volatile("cp.async.bulk.commit_group;" ::: "memory");
        asm volatile("cp.async.bulk.wait_group 0;" ::: "memory");
    }
}

extern "C" void kernel_launch(void* const* d_in, const int* in_sizes, int n_in,
                              void* d_out, int out_size) {
    const float* user_emb = (const float*)d_in[0];
    const float* item_emb = (const float*)d_in[1];
    float* out = (float*)d_out;
    const int B = in_sizes[1] / PARAMS;        // 16384
    can_kernel<<<B / SPC, THREADS>>>(user_emb, item_emb, out);
}

// round 10
// speedup vs baseline: 1.6648x; 1.0370x over previous
#include <cuda_runtime.h>

// CAN co-action unit: per-sample 2-layer MLP, D=16, N=50, B=16384.
// R3 champion data path (direct strided x LDG, broadcast weight LDS.128 from
// 552-word-padded smem, scalar fmaf, 2 same-sample rows/thread, plain STG),
// with register pressure trimmed (weight rows in 2 float4 halves) and
// __launch_bounds__(224,4) to fit 4 CTAs/SM -> 28 warps/SM (+33% warp supply
// to cover LDS/LDG latency and push the fma pipe toward its 2/cyc rate).

#define D 16
#define N 50
#define PARAMS 544            // 2*(256+16)
#define PSTRIDE 552           // padded param stride (words); %32==8 bank shift
#define SPC 8                 // samples per CTA
#define TPS 25                // threads per sample (2 rows each)
#define THREADS 224
#define ACTIVE (SPC * TPS)    // 200
#define CTA_ROWS (SPC * N)    // 400
#define PWORDS (SPC * PSTRIDE)   // 4416

__global__ __launch_bounds__(THREADS, 4) void can_kernel(
    const float* __restrict__ user_emb,
    const float* __restrict__ item_emb,
    float* __restrict__ out)
{
    __shared__ float sp[PWORDS];   // W0|b0|W1|b1 per sample, padded stride

    const int t = threadIdx.x;

    // ---- Stage params for 8 samples (136 float4 each), coalesced.
    {
        const float4* src = (const float4*)(item_emb + (size_t)blockIdx.x * SPC * PARAMS);
        #pragma unroll
        for (int k = 0; k < 5; k++) {
            int i = t + k * THREADS;
            if (i < SPC * (PARAMS / 4)) {
                int si = i / (PARAMS / 4);
                int wi = i - si * (PARAMS / 4);
                *(float4*)(sp + si * PSTRIDE + wi * 4) = src[i];
            }
        }
    }

    // ---- This thread's two rows (same sample): rows j and j+25 of sample s.
    const int s = t / TPS;
    const int j = t - s * TPS;
    const bool active = (t < ACTIVE);

    const size_t grow = (size_t)blockIdx.x * CTA_ROWS + s * N + j;
    float x0[D], x1[D];
    if (active) {
        const float4* r0 = (const float4*)(user_emb + grow * D);
        const float4* r1 = (const float4*)(user_emb + (grow + TPS) * D);
        #pragma unroll
        for (int q = 0; q < 4; q++) {
            float4 a = r0[q], b = r1[q];
            x0[q*4+0]=a.x; x0[q*4+1]=a.y; x0[q*4+2]=a.z; x0[q*4+3]=a.w;
            x1[q*4+0]=b.x; x1[q*4+1]=b.y; x1[q*4+2]=b.z; x1[q*4+3]=b.w;
        }
    }
    __syncthreads();

    if (!active) return;

    const float* p = sp + s * PSTRIDE;
    float a0[D], a1[D];

    // ---- Layer 1: relu(x W0 + b0).  W0 = p[0..255], b0 = p[256..271].
    {
        const float4* bias = (const float4*)(p + 256);
        #pragma unroll
        for (int q = 0; q < 4; q++) {
            float4 v = bias[q];
            a0[q*4+0]=v.x; a0[q*4+1]=v.y; a0[q*4+2]=v.z; a0[q*4+3]=v.w;
            a1[q*4+0]=v.x; a1[q*4+1]=v.y; a1[q*4+2]=v.z; a1[q*4+3]=v.w;
        }
        #pragma unroll
        for (int d = 0; d < D; d++) {
            const float4* wr = (const float4*)(p + d * D);
            const float u0 = x0[d], u1 = x1[d];
            // First half: outputs 0..7 (2 float4 of W live at a time).
            {
                float4 wA = wr[0], wB = wr[1];
                a0[0]=fmaf(u0,wA.x,a0[0]); a1[0]=fmaf(u1,wA.x,a1[0]);
                a0[1]=fmaf(u0,wA.y,a0[1]); a1[1]=fmaf(u1,wA.y,a1[1]);
                a0[2]=fmaf(u0,wA.z,a0[2]); a1[2]=fmaf(u1,wA.z,a1[2]);
                a0[3]=fmaf(u0,wA.w,a0[3]); a1[3]=fmaf(u1,wA.w,a1[3]);
                a0[4]=fmaf(u0,wB.x,a0[4]); a1[4]=fmaf(u1,wB.x,a1[4]);
                a0[5]=fmaf(u0,wB.y,a0[5]); a1[5]=fmaf(u1,wB.y,a1[5]);
                a0[6]=fmaf(u0,wB.z,a0[6]); a1[6]=fmaf(u1,wB.z,a1[6]);
                a0[7]=fmaf(u0,wB.w,a0[7]); a1[7]=fmaf(u1,wB.w,a1[7]);
            }
            // Second half: outputs 8..15.
            {
                float4 wC = wr[2], wE = wr[3];
                a0[8] =fmaf(u0,wC.x,a0[8]);  a1[8] =fmaf(u1,wC.x,a1[8]);
                a0[9] =fmaf(u0,wC.y,a0[9]);  a1[9] =fmaf(u1,wC.y,a1[9]);
                a0[10]=fmaf(u0,wC.z,a0[10]); a1[10]=fmaf(u1,wC.z,a1[10]);
                a0[11]=fmaf(u0,wC.w,a0[11]); a1[11]=fmaf(u1,wC.w,a1[11]);
                a0[12]=fmaf(u0,wE.x,a0[12]); a1[12]=fmaf(u1,wE.x,a1[12]);
                a0[13]=fmaf(u0,wE.y,a0[13]); a1[13]=fmaf(u1,wE.y,a1[13]);
                a0[14]=fmaf(u0,wE.z,a0[14]); a1[14]=fmaf(u1,wE.z,a1[14]);
                a0[15]=fmaf(u0,wE.w,a0[15]); a1[15]=fmaf(u1,wE.w,a1[15]);
            }
        }
        #pragma unroll
        for (int e = 0; e < D; e++) {
            x0[e] = fmaxf(a0[e], 0.0f);
            x1[e] = fmaxf(a1[e], 0.0f);
        }
    }

    // ---- Layer 2: x W1 + b1.  W1 = p[272..527], b1 = p[528..543].
    {
        const float4* bias = (const float4*)(p + 528);
        #pragma unroll
        for (int q = 0; q < 4; q++) {
            float4 v = bias[q];
            a0[q*4+0]=v.x; a0[q*4+1]=v.y; a0[q*4+2]=v.z; a0[q*4+3]=v.w;
            a1[q*4+0]=v.x; a1[q*4+1]=v.y; a1[q*4+2]=v.z; a1[q*4+3]=v.w;
        }
        #pragma unroll
        for (int d = 0; d < D; d++) {
            const float4* wr = (const float4*)(p + 272 + d * D);
            const float u0 = x0[d], u1 = x1[d];
            {
                float4 wA = wr[0], wB = wr[1];
                a0[0]=fmaf(u0,wA.x,a0[0]); a1[0]=fmaf(u1,wA.x,a1[0]);
                a0[1]=fmaf(u0,wA.y,a0[1]); a1[1]=fmaf(u1,wA.y,a1[1]);
                a0[2]=fmaf(u0,wA.z,a0[2]); a1[2]=fmaf(u1,wA.z,a1[2]);
                a0[3]=fmaf(u0,wA.w,a0[3]); a1[3]=fmaf(u1,wA.w,a1[3]);
                a0[4]=fmaf(u0,wB.x,a0[4]); a1[4]=fmaf(u1,wB.x,a1[4]);
                a0[5]=fmaf(u0,wB.y,a0[5]); a1[5]=fmaf(u1,wB.y,a1[5]);
                a0[6]=fmaf(u0,wB.z,a0[6]); a1[6]=fmaf(u1,wB.z,a1[6]);
                a0[7]=fmaf(u0,wB.w,a0[7]); a1[7]=fmaf(u1,wB.w,a1[7]);
            }
            {
                float4 wC = wr[2], wE = wr[3];
                a0[8] =fmaf(u0,wC.x,a0[8]);  a1[8] =fmaf(u1,wC.x,a1[8]);
                a0[9] =fmaf(u0,wC.y,a0[9]);  a1[9] =fmaf(u1,wC.y,a1[9]);
                a0[10]=fmaf(u0,wC.z,a0[10]); a1[10]=fmaf(u1,wC.z,a1[10]);
                a0[11]=fmaf(u0,wC.w,a0[11]); a1[11]=fmaf(u1,wC.w,a1[11]);
                a0[12]=fmaf(u0,wE.x,a0[12]); a1[12]=fmaf(u1,wE.x,a1[12]);
                a0[13]=fmaf(u0,wE.y,a0[13]); a1[13]=fmaf(u1,wE.y,a1[13]);
                a0[14]=fmaf(u0,wE.z,a0[14]); a1[14]=fmaf(u1,wE.z,a1[14]);
                a0[15]=fmaf(u0,wE.w,a0[15]); a1[15]=fmaf(u1,wE.w,a1[15]);
            }
        }
    }

    // ---- Relu + store both rows (4x STG.128 each, fire-and-forget).
    {
        float4* o0 = (float4*)(out + grow * D);
        float4* o1 = (float4*)(out + (grow + TPS) * D);
        #pragma unroll
        for (int q = 0; q < 4; q++) {
            float4 v0 = { fmaxf(a0[q*4+0],0.f), fmaxf(a0[q*4+1],0.f),
                          fmaxf(a0[q*4+2],0.f), fmaxf(a0[q*4+3],0.f) };
            float4 v1 = { fmaxf(a1[q*4+0],0.f), fmaxf(a1[q*4+1],0.f),
                          fmaxf(a1[q*4+2],0.f), fmaxf(a1[q*4+3],0.f) };
            o0[q] = v0;
            o1[q] = v1;
        }
    }
}

extern "C" void kernel_launch(void* const* d_in, const int* in_sizes, int n_in,
                              void* d_out, int out_size) {
    const float* user_emb = (const float*)d_in[0];
    const float* item_emb = (const float*)d_in[1];
    float* out = (float*)d_out;
    const int B = in_sizes[1] / PARAMS;        // 16384
    can_kernel<<<B / SPC, THREADS>>>(user_emb, item_emb, out);
}